// round 7
// baseline (speedup 1.0000x reference)
#include <cuda_runtime.h>

typedef unsigned long long u64;

#define N_EDGES_CAP 160000
__device__ float g_mix[(size_t)N_EDGES_CAP * 256];

#define TE 64
#define TPB_A 128
#define SMEM_A_FLOATS 16384   // sA(4096) + sB(4096) + sWdup(8192 floats = 4096 u64)

// ---------- packed f32x2 helpers ----------
__device__ __forceinline__ u64 ffma2(u64 a, u64 b, u64 c) {
    u64 d; asm("fma.rn.f32x2 %0, %1, %2, %3;" : "=l"(d) : "l"(a), "l"(b), "l"(c)); return d;
}
__device__ __forceinline__ void unpack2(float& lo, float& hi, u64 v) {
    asm("mov.b64 {%0, %1}, %2;" : "=f"(lo), "=f"(hi) : "l"(v));
}

__device__ __forceinline__ void red4(float* p, float a, float b, float c, float d) {
    asm volatile("red.global.add.v4.f32 [%0], {%1, %2, %3, %4};"
                 :: "l"(p), "f"(a), "f"(b), "f"(c), "f"(d) : "memory");
}

__device__ __forceinline__ float silu(float x) {
    return __fdividef(x, 1.0f + __expf(-x));
}

// GEMM, edge-paired: acc[p*4+jj] = pair(edges eoff+2p, eoff+2p+1) x col joff+jj.
// A loaded as u64 pairs from plain float sIn[k][64]; B from pre-duplicated sWd.
template<int K>
__device__ __forceinline__ void gemmE(const float* __restrict__ sIn,
                                      const u64* __restrict__ sWd,
                                      int eoff, int joff, u64 (&acc)[16])
{
    #pragma unroll
    for (int m = 0; m < 16; m++) acc[m] = 0ull;
    #pragma unroll 16
    for (int k = 0; k < K; k++) {
        const ulonglong2* ap = (const ulonglong2*)(sIn + k * 64 + eoff);
        ulonglong2 aA = ap[0], aB = ap[1];           // edge-pairs p0..p3
        const ulonglong2* bp = (const ulonglong2*)(sWd + k * 64 + joff);
        ulonglong2 b0 = bp[0], b1 = bp[1];           // dup cols j0,j1 ; j2,j3
        acc[0]  = ffma2(aA.x, b0.x, acc[0]);
        acc[1]  = ffma2(aA.x, b0.y, acc[1]);
        acc[2]  = ffma2(aA.x, b1.x, acc[2]);
        acc[3]  = ffma2(aA.x, b1.y, acc[3]);
        acc[4]  = ffma2(aA.y, b0.x, acc[4]);
        acc[5]  = ffma2(aA.y, b0.y, acc[5]);
        acc[6]  = ffma2(aA.y, b1.x, acc[6]);
        acc[7]  = ffma2(aA.y, b1.y, acc[7]);
        acc[8]  = ffma2(aB.x, b0.x, acc[8]);
        acc[9]  = ffma2(aB.x, b0.y, acc[9]);
        acc[10] = ffma2(aB.x, b1.x, acc[10]);
        acc[11] = ffma2(aB.x, b1.y, acc[11]);
        acc[12] = ffma2(aB.y, b0.x, acc[12]);
        acc[13] = ffma2(aB.y, b0.y, acc[13]);
        acc[14] = ffma2(aB.y, b1.x, acc[14]);
        acc[15] = ffma2(aB.y, b1.y, acc[15]);
    }
}

// Epilogue: silu(acc*scale)*post, store TRANSPOSED plain-float sOut[j][e].
__device__ __forceinline__ void epiT(u64 (&acc)[16], float scale, float post,
                                     float* __restrict__ sOut, int eoff, int joff)
{
    float f[8][4];
    #pragma unroll
    for (int p = 0; p < 4; p++)
        #pragma unroll
        for (int jj = 0; jj < 4; jj++)
            unpack2(f[2*p][jj], f[2*p+1][jj], acc[p*4 + jj]);
    #pragma unroll
    for (int e = 0; e < 8; e++)
        #pragma unroll
        for (int jj = 0; jj < 4; jj++)
            f[e][jj] = silu(f[e][jj] * scale) * post;
    #pragma unroll
    for (int jj = 0; jj < 4; jj++) {
        float4 a = make_float4(f[0][jj], f[1][jj], f[2][jj], f[3][jj]);
        float4 b = make_float4(f[4][jj], f[5][jj], f[6][jj], f[7][jj]);
        *(float4*)(sOut + (joff + jj) * 64 + eoff)     = a;
        *(float4*)(sOut + (joff + jj) * 64 + eoff + 4) = b;
    }
}

// Layer-4 epilogue: raw acc -> sMix[e][64]
__device__ __forceinline__ void epiMix(u64 (&acc)[16], float* __restrict__ sMix,
                                       int eoff, int joff)
{
    #pragma unroll
    for (int p = 0; p < 4; p++) {
        float f0[4], f1[4];
        #pragma unroll
        for (int jj = 0; jj < 4; jj++) unpack2(f0[jj], f1[jj], acc[p*4 + jj]);
        *(float4*)(sMix + (eoff + 2*p    ) * 64 + joff) = make_float4(f0[0], f0[1], f0[2], f0[3]);
        *(float4*)(sMix + (eoff + 2*p + 1) * 64 + joff) = make_float4(f1[0], f1[1], f1[2], f1[3]);
    }
}

// Stage 8 float4 of a 64x64 weight tile from prefetched regs into dup smem.
__device__ __forceinline__ void stsDup(const float4 (&pre)[8], u64* __restrict__ sWd, int tid)
{
    #pragma unroll
    for (int i = 0; i < 8; i++) {
        int idx = tid + i * TPB_A;   // float4 index 0..1023 (float idx = u64 idx = idx*4)
        float4 w = pre[i];
        ((float4*)sWd)[idx*2]     = make_float4(w.x, w.x, w.y, w.y);
        ((float4*)sWd)[idx*2 + 1] = make_float4(w.z, w.z, w.w, w.w);
    }
}

// ===================== Kernel A: edge-paired tiled-GEMM MLP -> mix =====================
__global__ void __launch_bounds__(TPB_A)
mlp_kernel(const float* __restrict__ radial,
           const float* __restrict__ w1, const float* __restrict__ w2,
           const float* __restrict__ w3, const float* __restrict__ w4,
           int n_edges)
{
    extern __shared__ float smem[];
    float* sA  = smem;                 // 4096 floats
    float* sB  = smem + 4096;          // 4096 floats
    u64*   sWd = (u64*)(smem + 8192);  // 4096 u64

    int tid = threadIdx.x;
    int e0 = blockIdx.x * TE;
    int eoff = (tid & 7) * 8;    // 8 e-groups of 8 edges
    int joff = (tid >> 3) * 4;   // 16 j-groups of 4 cols

    // stage radial transposed into sA[k][e] (k<8), zero-fill tail edges
    {
        int e  = tid >> 1;
        int kh = (tid & 1) * 4;
        int ge = e0 + e;
        float4 v = make_float4(0.f, 0.f, 0.f, 0.f);
        if (ge < n_edges) v = *(const float4*)(radial + (size_t)ge * 8 + kh);
        sA[(kh + 0) * 64 + e] = v.x;
        sA[(kh + 1) * 64 + e] = v.y;
        sA[(kh + 2) * 64 + e] = v.z;
        sA[(kh + 3) * 64 + e] = v.w;
    }
    // stage w1 (8x64) duplicated
    {
        float4 w = ((const float4*)w1)[tid];          // 128 float4 = 512 floats
        ((float4*)sWd)[tid*2]     = make_float4(w.x, w.x, w.y, w.y);
        ((float4*)sWd)[tid*2 + 1] = make_float4(w.z, w.z, w.w, w.w);
    }
    __syncthreads();

    u64 acc[16];
    float4 pre[8];

    // ---- layer 1 (K=8, scale 1/sqrt(8)); prefetch w2 ----
    #pragma unroll
    for (int i = 0; i < 8; i++) pre[i] = ((const float4*)w2)[tid + i * TPB_A];
    gemmE<8>(sA, sWd, eoff, joff, acc);
    epiT(acc, 0.35355339059327373f, 1.0f, sB, eoff, joff);
    __syncthreads();
    stsDup(pre, sWd, tid);
    __syncthreads();

    // ---- layer 2; prefetch w3 ----
    #pragma unroll
    for (int i = 0; i < 8; i++) pre[i] = ((const float4*)w3)[tid + i * TPB_A];
    gemmE<64>(sB, sWd, eoff, joff, acc);
    epiT(acc, 0.125f, 1.0f, sA, eoff, joff);
    __syncthreads();
    stsDup(pre, sWd, tid);
    __syncthreads();

    // ---- layer 3 (fold (1/8)*(1/sqrt16)=1/32 into h3); prefetch w4 chunk 0 ----
    #pragma unroll
    for (int i = 0; i < 8; i++) {
        int idx = tid + i * TPB_A;
        int row = idx >> 4, col = idx & 15;
        pre[i] = *(const float4*)(w4 + (size_t)row * 256 + col * 4);
    }
    gemmE<64>(sA, sWd, eoff, joff, acc);
    epiT(acc, 0.125f, 0.03125f, sB, eoff, joff);
    __syncthreads();
    stsDup(pre, sWd, tid);
    __syncthreads();

    // ---- layer 4: mix = h3 @ w4 in 4 chunks of 64 cols; h3 stays in sB ----
    #pragma unroll 1
    for (int c = 0; c < 4; c++) {
        gemmE<64>(sB, sWd, eoff, joff, acc);
        if (c < 3) {
            #pragma unroll
            for (int i = 0; i < 8; i++) {
                int idx = tid + i * TPB_A;
                int row = idx >> 4, col = idx & 15;
                pre[i] = *(const float4*)(w4 + (size_t)row * 256 + (c + 1) * 64 + col * 4);
            }
        }
        epiMix(acc, sA, eoff, joff);      // sMix = sA region
        __syncthreads();
        // coalesced copy sMix -> g_mix chunk c
        #pragma unroll
        for (int i = 0; i < 8; i++) {
            int idx = tid + i * TPB_A;    // float4 idx 0..1023
            int row = idx >> 4, col = idx & 15;
            int ge = e0 + row;
            if (ge < n_edges)
                *(float4*)(g_mix + (size_t)ge * 256 + c * 64 + col * 4) =
                    ((float4*)sA)[idx];
        }
        if (c < 3) stsDup(pre, sWd, tid);
        __syncthreads();
    }
}

// ===================== Kernel B: tensor product + coalesced scatter =====================
// Position p in [0,1024): irrep regions
//   r0 [0,64)    W=1  t[p]
//   r1 [64,256)  W=3  tbase=64  ybase=0
//   r2 [256,576) W=5  tbase=128 ybase=3
//   r3 [576,1024)W=7  tbase=192 ybase=8
template<int W, int START, int TB, int YB, int MUL>
__device__ __forceinline__ float tpv(const float* tsh, const float* ysh, int p) {
    int pp = p - START;
    int c = (pp * MUL) >> 16;
    int k = pp - c * W;
    return tsh[TB + c] * ysh[YB + k];
}

#define TPB_B 256

__global__ void __launch_bounds__(TPB_B)
scatter_kernel(const float* __restrict__ vectors,
               const float* __restrict__ node_feats,
               const int* __restrict__ senders,
               const int* __restrict__ receivers,
               float* __restrict__ out, int n_edges)
{
    __shared__ float stage[TPB_B / 32][272];   // per-warp: t[256] + y[15]
    int warp = threadIdx.x >> 5, lane = threadIdx.x & 31;
    int e = blockIdx.x * (TPB_B / 32) + warp;
    if (e >= n_edges) return;

    float* tsh = stage[warp];
    float* ysh = tsh + 256;

    int snd = __ldg(senders + e), rcv = __ldg(receivers + e);

    // t[c] = node_feats[snd][c & 63] * mix[e][c]
    {
        const float4* mp = (const float4*)(g_mix + (size_t)e * 256) + lane * 2;
        float4 m0 = __ldg(mp), m1 = __ldg(mp + 1);
        const float4* sp = (const float4*)(node_feats + (size_t)snd * 64) + (lane & 7) * 2;
        float4 s0 = __ldg(sp), s1 = __ldg(sp + 1);
        float4 t0 = make_float4(m0.x*s0.x, m0.y*s0.y, m0.z*s0.z, m0.w*s0.w);
        float4 t1 = make_float4(m1.x*s1.x, m1.y*s1.y, m1.z*s1.z, m1.w*s1.w);
        ((float4*)tsh)[lane*2]     = t0;
        ((float4*)tsh)[lane*2 + 1] = t1;
    }

    // spherical harmonics (lane 0 stores 15 floats)
    {
        float vx = __ldg(vectors + 3*(size_t)e + 0);
        float vy = __ldg(vectors + 3*(size_t)e + 1);
        float vz = __ldg(vectors + 3*(size_t)e + 2);
        float inv = 1.0f / (sqrtf(vx*vx + vy*vy + vz*vz) + 1e-12f);
        float x = vx*inv, y = vy*inv, z = vz*inv;
        const float s3  = 1.7320508075688772f;
        const float s5  = 2.23606797749979f;
        const float s15 = 3.872983346207417f;
        const float c33 = 2.091650066335189f;
        const float c32 = 10.246950765959598f;
        const float c31 = 1.6201851746019651f;
        const float c30 = 1.3228756555322954f;
        float z2 = z*z, x2 = x*x, y2 = y*y;
        if (lane == 0) {
            ysh[0]  = s3 * y;  ysh[1] = s3 * z;  ysh[2] = s3 * x;
            ysh[3]  = s15 * x * y;
            ysh[4]  = s15 * y * z;
            ysh[5]  = 0.5f * s5 * (3.0f * z2 - 1.0f);
            ysh[6]  = s15 * x * z;
            ysh[7]  = 0.5f * s15 * (x2 - y2);
            ysh[8]  = c33 * y * (3.0f * x2 - y2);
            ysh[9]  = c32 * x * y * z;
            ysh[10] = c31 * y * (5.0f * z2 - 1.0f);
            ysh[11] = c30 * z * (5.0f * z2 - 3.0f);
            ysh[12] = c31 * x * (5.0f * z2 - 1.0f);
            ysh[13] = 0.5f * c32 * z * (x2 - y2);
            ysh[14] = c33 * x * (x2 - 3.0f * y2);
        }
    }
    __syncwarp();

    float* ob = out + (size_t)rcv * 1024;

    #pragma unroll
    for (int j = 0; j < 8; j++) {
        int p0 = j * 128 + lane * 4;
        float v0, v1, v2, v3;
        if (j == 0) {
            if (lane < 16) {  // r0: scalars, y=1
                v0 = tsh[p0]; v1 = tsh[p0+1]; v2 = tsh[p0+2]; v3 = tsh[p0+3];
            } else {          // r1
                v0 = tpv<3,64,64,0,21846>(tsh, ysh, p0);
                v1 = tpv<3,64,64,0,21846>(tsh, ysh, p0+1);
                v2 = tpv<3,64,64,0,21846>(tsh, ysh, p0+2);
                v3 = tpv<3,64,64,0,21846>(tsh, ysh, p0+3);
            }
        } else if (j == 1) {  // r1
            v0 = tpv<3,64,64,0,21846>(tsh, ysh, p0);
            v1 = tpv<3,64,64,0,21846>(tsh, ysh, p0+1);
            v2 = tpv<3,64,64,0,21846>(tsh, ysh, p0+2);
            v3 = tpv<3,64,64,0,21846>(tsh, ysh, p0+3);
        } else if (j == 2 || j == 3) {  // r2
            v0 = tpv<5,256,128,3,13108>(tsh, ysh, p0);
            v1 = tpv<5,256,128,3,13108>(tsh, ysh, p0+1);
            v2 = tpv<5,256,128,3,13108>(tsh, ysh, p0+2);
            v3 = tpv<5,256,128,3,13108>(tsh, ysh, p0+3);
        } else if (j == 4) {
            if (lane < 16) {  // r2 tail
                v0 = tpv<5,256,128,3,13108>(tsh, ysh, p0);
                v1 = tpv<5,256,128,3,13108>(tsh, ysh, p0+1);
                v2 = tpv<5,256,128,3,13108>(tsh, ysh, p0+2);
                v3 = tpv<5,256,128,3,13108>(tsh, ysh, p0+3);
            } else {          // r3 head
                v0 = tpv<7,576,192,8,9363>(tsh, ysh, p0);
                v1 = tpv<7,576,192,8,9363>(tsh, ysh, p0+1);
                v2 = tpv<7,576,192,8,9363>(tsh, ysh, p0+2);
                v3 = tpv<7,576,192,8,9363>(tsh, ysh, p0+3);
            }
        } else {              // r3
            v0 = tpv<7,576,192,8,9363>(tsh, ysh, p0);
            v1 = tpv<7,576,192,8,9363>(tsh, ysh, p0+1);
            v2 = tpv<7,576,192,8,9363>(tsh, ysh, p0+2);
            v3 = tpv<7,576,192,8,9363>(tsh, ysh, p0+3);
        }
        red4(ob + p0, v0, v1, v2, v3);
    }
}

extern "C" void kernel_launch(void* const* d_in, const int* in_sizes, int n_in,
                              void* d_out, int out_size)
{
    const float* vectors    = (const float*)d_in[0];
    const float* node_feats = (const float*)d_in[1];
    const float* radial     = (const float*)d_in[2];
    const float* w1         = (const float*)d_in[3];
    const float* w2         = (const float*)d_in[4];
    const float* w3         = (const float*)d_in[5];
    const float* w4         = (const float*)d_in[6];
    const int*   senders    = (const int*)d_in[7];
    const int*   receivers  = (const int*)d_in[8];
    float* out = (float*)d_out;

    int n_edges = in_sizes[7];

    cudaFuncSetAttribute(mlp_kernel,
                         cudaFuncAttributeMaxDynamicSharedMemorySize,
                         SMEM_A_FLOATS * sizeof(float));

    cudaMemsetAsync(d_out, 0, (size_t)out_size * sizeof(float));

    int grid_a = (n_edges + TE - 1) / TE;
    mlp_kernel<<<grid_a, TPB_A, SMEM_A_FLOATS * sizeof(float)>>>(
        radial, w1, w2, w3, w4, n_edges);

    int edges_per_blk = TPB_B / 32;
    int grid_b = (n_edges + edges_per_blk - 1) / edges_per_blk;
    scatter_kernel<<<grid_b, TPB_B>>>(vectors, node_feats, senders, receivers,
                                      out, n_edges);
}

// round 8
// speedup vs baseline: 1.4021x; 1.4021x over previous
#include <cuda_runtime.h>

typedef unsigned long long u64;

#define TE 64
#define TPB_A 128
// smem floats: sA(4096) + sB(4096) + sW(4096) + sY(1024) + sSnd(64) + sRcv(64)
#define SMEM_FLOATS (4096 + 4096 + 4096 + 1024 + 64 + 64)

// ---------- packed f32x2 helpers ----------
__device__ __forceinline__ u64 pack2(float a, float b) {
    u64 r; asm("mov.b64 %0, {%1, %2};" : "=l"(r) : "f"(a), "f"(b)); return r;
}
__device__ __forceinline__ u64 bcast2(float a) { return pack2(a, a); }
__device__ __forceinline__ u64 ffma2(u64 a, u64 b, u64 c) {
    u64 d; asm("fma.rn.f32x2 %0, %1, %2, %3;" : "=l"(d) : "l"(a), "l"(b), "l"(c)); return d;
}
__device__ __forceinline__ void unpack2(float& lo, float& hi, u64 v) {
    asm("mov.b64 {%0, %1}, %2;" : "=f"(lo), "=f"(hi) : "l"(v));
}

__device__ __forceinline__ void red4(float* p, float a, float b, float c, float d) {
    asm volatile("red.global.add.v4.f32 [%0], {%1, %2, %3, %4};"
                 :: "l"(p), "f"(a), "f"(b), "f"(c), "f"(d) : "memory");
}

__device__ __forceinline__ float silu(float x) {
    return __fdividef(x, 1.0f + __expf(-x));
}

// GEMM: C[4 edges][8 cols] += sIn[k][e] * sWt[k][j]  (round-6 proven shape)
template<int K>
__device__ __forceinline__ void gemm16(const float* __restrict__ sIn,
                                       const float* __restrict__ sWt,
                                       int eoff, int joff, u64 (&acc)[16])
{
    #pragma unroll
    for (int m = 0; m < 16; m++) acc[m] = 0ull;
    #pragma unroll 8
    for (int k = 0; k < K; k++) {
        float4 av = *(const float4*)(sIn + k * 64 + eoff);
        const ulonglong2* bp = (const ulonglong2*)(sWt + k * 64 + joff);
        ulonglong2 b0 = bp[0], b1 = bp[1];
        u64 a0 = bcast2(av.x), a1 = bcast2(av.y), a2 = bcast2(av.z), a3 = bcast2(av.w);
        acc[0]  = ffma2(a0, b0.x, acc[0]);
        acc[1]  = ffma2(a0, b0.y, acc[1]);
        acc[2]  = ffma2(a0, b1.x, acc[2]);
        acc[3]  = ffma2(a0, b1.y, acc[3]);
        acc[4]  = ffma2(a1, b0.x, acc[4]);
        acc[5]  = ffma2(a1, b0.y, acc[5]);
        acc[6]  = ffma2(a1, b1.x, acc[6]);
        acc[7]  = ffma2(a1, b1.y, acc[7]);
        acc[8]  = ffma2(a2, b0.x, acc[8]);
        acc[9]  = ffma2(a2, b0.y, acc[9]);
        acc[10] = ffma2(a2, b1.x, acc[10]);
        acc[11] = ffma2(a2, b1.y, acc[11]);
        acc[12] = ffma2(a3, b0.x, acc[12]);
        acc[13] = ffma2(a3, b0.y, acc[13]);
        acc[14] = ffma2(a3, b1.x, acc[14]);
        acc[15] = ffma2(a3, b1.y, acc[15]);
    }
}

// Epilogue: silu(acc*scale)*post, store TRANSPOSED sOut[j][e].
__device__ __forceinline__ void epiT(u64 (&acc)[16], float scale, float post,
                                     float* __restrict__ sOut, int eoff, int joff)
{
    float c[4][8];
    #pragma unroll
    for (int ei = 0; ei < 4; ei++)
        #pragma unroll
        for (int jp = 0; jp < 4; jp++)
            unpack2(c[ei][2*jp], c[ei][2*jp+1], acc[ei*4 + jp]);
    #pragma unroll
    for (int ei = 0; ei < 4; ei++)
        #pragma unroll
        for (int jj = 0; jj < 8; jj++)
            c[ei][jj] = silu(c[ei][jj] * scale) * post;
    #pragma unroll
    for (int jj = 0; jj < 8; jj++) {
        float4 v = make_float4(c[0][jj], c[1][jj], c[2][jj], c[3][jj]);
        *(float4*)(sOut + (joff + jj) * 64 + eoff) = v;
    }
}

// Layer-4 epilogue: raw acc -> sMix[e][64]
__device__ __forceinline__ void epiMix(u64 (&acc)[16], float* __restrict__ sMix,
                                       int eoff, int joff)
{
    #pragma unroll
    for (int ei = 0; ei < 4; ei++) {
        float4 v0, v1;
        unpack2(v0.x, v0.y, acc[ei*4 + 0]);
        unpack2(v0.z, v0.w, acc[ei*4 + 1]);
        unpack2(v1.x, v1.y, acc[ei*4 + 2]);
        unpack2(v1.z, v1.w, acc[ei*4 + 3]);
        *(float4*)(sMix + (eoff + ei) * 64 + joff)     = v0;
        *(float4*)(sMix + (eoff + ei) * 64 + joff + 4) = v1;
    }
}

// Per-chunk tensor-product + coalesced vector-reduce scatter for one irrep.
// Region length 64*W floats at out[rcv*1024 + BASE], position q: ch=q/W, k=q%W.
template<int W, int YB, int MUL, int BASE>
__device__ __forceinline__ void scat(const float* __restrict__ sMix,
                                     const float* __restrict__ sY,
                                     const int* __restrict__ sSnd,
                                     const int* __restrict__ sRcv,
                                     const float* __restrict__ nf,
                                     float* __restrict__ out,
                                     int warp, int lane, int e0, int n_edges)
{
    #pragma unroll 1
    for (int sub = 0; sub < 16; sub++) {
        int e = warp * 16 + sub;
        if (e0 + e >= n_edges) break;
        int snd = sSnd[e], rcv = sRcv[e];
        const float* mrow = sMix + e * 64;
        const float* nfrow = nf + (size_t)snd * 64;
        const float* yrow = sY + e * 16 + YB;
        float* ob = out + (size_t)rcv * 1024 + BASE;
        constexpr int L = 64 * W;
        constexpr int NR = (L + 127) / 128;
        #pragma unroll
        for (int r = 0; r < NR; r++) {
            bool half = (L % 128 != 0) && (r == NR - 1);
            if (half && lane >= 16) continue;
            int q0 = r * 128 + lane * 4;
            float v[4];
            #pragma unroll
            for (int j = 0; j < 4; j++) {
                int q = q0 + j;
                int ch = (q * MUL) >> 16;   // q / W
                int k = q - ch * W;
                float t = mrow[ch] * __ldg(nfrow + ch);
                v[j] = (W == 1) ? t : t * yrow[k];
            }
            red4(ob + q0, v[0], v[1], v[2], v[3]);
        }
    }
}

// ===================== fused kernel: MLP GEMM + TP + scatter =====================
__global__ void __launch_bounds__(TPB_A)
fused_kernel(const float* __restrict__ vectors,
             const float* __restrict__ node_feats,
             const float* __restrict__ radial,
             const float* __restrict__ w1, const float* __restrict__ w2,
             const float* __restrict__ w3, const float* __restrict__ w4,
             const int* __restrict__ senders, const int* __restrict__ receivers,
             float* __restrict__ out, int n_edges)
{
    extern __shared__ float smem[];
    float* sA   = smem;            // 4096
    float* sB   = smem + 4096;     // 4096
    float* sW   = smem + 8192;     // 4096
    float* sY   = smem + 12288;    // 1024 (64 edges x 16)
    int*   sSnd = (int*)(smem + 13312);  // 64
    int*   sRcv = (int*)(smem + 13376);  // 64

    int tid = threadIdx.x;
    int warp = tid >> 5, lane = tid & 31;
    int e0 = blockIdx.x * TE;
    int eoff = (tid & 15) * 4;
    int joff = (tid >> 4) * 8;

    // ---- prologue: stage radial (transposed), w1, indices, spherical harmonics ----
    {
        int e  = tid >> 1;
        int kh = (tid & 1) * 4;
        int ge = e0 + e;
        float4 v = make_float4(0.f, 0.f, 0.f, 0.f);
        if (ge < n_edges) v = *(const float4*)(radial + (size_t)ge * 8 + kh);
        sA[(kh + 0) * 64 + e] = v.x;
        sA[(kh + 1) * 64 + e] = v.y;
        sA[(kh + 2) * 64 + e] = v.z;
        sA[(kh + 3) * 64 + e] = v.w;
    }
    ((float4*)sW)[tid] = ((const float4*)w1)[tid];

    if (tid < 64) {
        int ge = e0 + tid;
        float vx = 0.f, vy = 0.f, vz = 1.f;
        int sn = 0;
        if (ge < n_edges) {
            vx = __ldg(vectors + 3*(size_t)ge + 0);
            vy = __ldg(vectors + 3*(size_t)ge + 1);
            vz = __ldg(vectors + 3*(size_t)ge + 2);
            sn = __ldg(senders + ge);
        }
        sSnd[tid] = sn;
        float inv = 1.0f / (sqrtf(vx*vx + vy*vy + vz*vz) + 1e-12f);
        float x = vx*inv, y = vy*inv, z = vz*inv;
        const float s3  = 1.7320508075688772f;
        const float s5  = 2.23606797749979f;
        const float s15 = 3.872983346207417f;
        const float c33 = 2.091650066335189f;
        const float c32 = 10.246950765959598f;
        const float c31 = 1.6201851746019651f;
        const float c30 = 1.3228756555322954f;
        float z2 = z*z, x2 = x*x, y2 = y*y;
        float* yr = sY + tid * 16;
        yr[0]  = s3 * y;  yr[1] = s3 * z;  yr[2] = s3 * x;
        yr[3]  = s15 * x * y;
        yr[4]  = s15 * y * z;
        yr[5]  = 0.5f * s5 * (3.0f * z2 - 1.0f);
        yr[6]  = s15 * x * z;
        yr[7]  = 0.5f * s15 * (x2 - y2);
        yr[8]  = c33 * y * (3.0f * x2 - y2);
        yr[9]  = c32 * x * y * z;
        yr[10] = c31 * y * (5.0f * z2 - 1.0f);
        yr[11] = c30 * z * (5.0f * z2 - 3.0f);
        yr[12] = c31 * x * (5.0f * z2 - 1.0f);
        yr[13] = 0.5f * c32 * z * (x2 - y2);
        yr[14] = c33 * x * (x2 - 3.0f * y2);
    } else {
        int e = tid - 64;
        int ge = e0 + e;
        sRcv[e] = (ge < n_edges) ? __ldg(receivers + ge) : 0;
    }
    __syncthreads();

    u64 acc[16];
    float4 pre[8];

    // ---- layer 1 (prefetch w2 during gemm) ----
    #pragma unroll
    for (int i = 0; i < 8; i++) pre[i] = ((const float4*)w2)[tid + i * TPB_A];
    gemm16<8>(sA, sW, eoff, joff, acc);
    epiT(acc, 0.35355339059327373f, 1.0f, sB, eoff, joff);
    __syncthreads();
    #pragma unroll
    for (int i = 0; i < 8; i++) ((float4*)sW)[tid + i * TPB_A] = pre[i];
    // prefetch w3
    #pragma unroll
    for (int i = 0; i < 8; i++) pre[i] = ((const float4*)w3)[tid + i * TPB_A];
    __syncthreads();

    // ---- layer 2 ----
    gemm16<64>(sB, sW, eoff, joff, acc);
    epiT(acc, 0.125f, 1.0f, sA, eoff, joff);
    __syncthreads();
    #pragma unroll
    for (int i = 0; i < 8; i++) ((float4*)sW)[tid + i * TPB_A] = pre[i];
    // prefetch w4 chunk 0
    #pragma unroll
    for (int i = 0; i < 8; i++) {
        int idx = tid + i * TPB_A;
        int row = idx >> 4, col = idx & 15;
        pre[i] = *(const float4*)(w4 + (size_t)row * 256 + col * 4);
    }
    __syncthreads();

    // ---- layer 3: h3 (fold (1/8)*(1/sqrt16) = 1/32) ----
    gemm16<64>(sA, sW, eoff, joff, acc);
    epiT(acc, 0.125f, 0.03125f, sB, eoff, joff);
    __syncthreads();
    #pragma unroll
    for (int i = 0; i < 8; i++) ((float4*)sW)[tid + i * TPB_A] = pre[i];
    // prefetch w4 chunk 1
    #pragma unroll
    for (int i = 0; i < 8; i++) {
        int idx = tid + i * TPB_A;
        int row = idx >> 4, col = idx & 15;
        pre[i] = *(const float4*)(w4 + (size_t)row * 256 + 64 + col * 4);
    }
    __syncthreads();

    // ---- layer 4 + fused scatter, chunk = irrep ----
    #pragma unroll 1
    for (int c = 0; c < 4; c++) {
        gemm16<64>(sB, sW, eoff, joff, acc);   // mix chunk c
        epiMix(acc, sA, eoff, joff);
        __syncthreads();
        if (c < 3) {   // stage next chunk's weights; prefetch the one after
            #pragma unroll
            for (int i = 0; i < 8; i++) ((float4*)sW)[tid + i * TPB_A] = pre[i];
            if (c < 2) {
                #pragma unroll
                for (int i = 0; i < 8; i++) {
                    int idx = tid + i * TPB_A;
                    int row = idx >> 4, col = idx & 15;
                    pre[i] = *(const float4*)(w4 + (size_t)row * 256 + (c + 2) * 64 + col * 4);
                }
            }
        }
        if (c == 0)
            scat<1, 0, 65536, 0>(sA, sY, sSnd, sRcv, node_feats, out, warp, lane, e0, n_edges);
        else if (c == 1)
            scat<3, 0, 21846, 64>(sA, sY, sSnd, sRcv, node_feats, out, warp, lane, e0, n_edges);
        else if (c == 2)
            scat<5, 3, 13108, 256>(sA, sY, sSnd, sRcv, node_feats, out, warp, lane, e0, n_edges);
        else
            scat<7, 8, 9363, 576>(sA, sY, sSnd, sRcv, node_feats, out, warp, lane, e0, n_edges);
        __syncthreads();
    }
}

extern "C" void kernel_launch(void* const* d_in, const int* in_sizes, int n_in,
                              void* d_out, int out_size)
{
    const float* vectors    = (const float*)d_in[0];
    const float* node_feats = (const float*)d_in[1];
    const float* radial     = (const float*)d_in[2];
    const float* w1         = (const float*)d_in[3];
    const float* w2         = (const float*)d_in[4];
    const float* w3         = (const float*)d_in[5];
    const float* w4         = (const float*)d_in[6];
    const int*   senders    = (const int*)d_in[7];
    const int*   receivers  = (const int*)d_in[8];
    float* out = (float*)d_out;

    int n_edges = in_sizes[7];

    cudaFuncSetAttribute(fused_kernel,
                         cudaFuncAttributeMaxDynamicSharedMemorySize,
                         SMEM_FLOATS * sizeof(float));

    cudaMemsetAsync(d_out, 0, (size_t)out_size * sizeof(float));

    int grid = (n_edges + TE - 1) / TE;
    fused_kernel<<<grid, TPB_A, SMEM_FLOATS * sizeof(float)>>>(
        vectors, node_feats, radial, w1, w2, w3, w4, senders, receivers,
        out, n_edges);
}